// round 7
// baseline (speedup 1.0000x reference)
#include <cuda_runtime.h>
#include <cuda_fp16.h>
#include <math.h>

// ---------------------------------------------------------------------------
// DRR ray integration, GB300.
// g_vol[z][y][x] holds a 2x2 (x,y)-face quad of the regulated density,
// quantized to u8:  u = round( v * 255/0.65 ),  v = sigmoid(d - 0.3).
//   quad bytes = ( u(x,y), u(x+1,y), u(x,y+1), u(x+1,y+1) )  in one uint.
// One trilinear tap = 2 x LDG.32 (faces at z and z+1); 70 MB volume is
// mostly L2-resident. u=0 maps to v=0 so zero-padded borders are exact.
// Decode: PRMT builds half2(1024+u) column pairs; x-lerp is done SIMD in
// fp16 (HSUB2+HFMA2, differences exact, one rounding <=0.5u), y/z in fp32.
// The affine (1024 offset, 0.65/255 scale) is corrected once per ray.
// ---------------------------------------------------------------------------

#define DIM 256
#define PITCH 260
#define PITCH2 (PITCH * PITCH)

#define V_SCALE (0.65f / 255.0f)      // v = u * V_SCALE
#define U_SCALE (255.0f / 0.65f)      // u = v * U_SCALE

__device__ unsigned g_vol[PITCH * PITCH * PITCH];  // ~70 MB, .bss zero-init
__device__ float    g_inv[12];                      // inv(affine)[:3,:4]

// ---------------------------------------------------------------------------
// 4x4 Gauss-Jordan inverse (single thread; runs inside pack kernel).
// ---------------------------------------------------------------------------
__device__ void invert_affine(const float* __restrict__ A) {
    float m[4][8];
#pragma unroll
    for (int r = 0; r < 4; r++)
#pragma unroll
        for (int c = 0; c < 4; c++) {
            m[r][c]     = A[r * 4 + c];
            m[r][c + 4] = (r == c) ? 1.0f : 0.0f;
        }
    for (int col = 0; col < 4; col++) {
        int piv = col;
        float best = fabsf(m[col][col]);
        for (int r = col + 1; r < 4; r++) {
            float v = fabsf(m[r][col]);
            if (v > best) { best = v; piv = r; }
        }
        if (piv != col)
            for (int c = 0; c < 8; c++) {
                float t = m[col][c]; m[col][c] = m[piv][c]; m[piv][c] = t;
            }
        float d = 1.0f / m[col][col];
        for (int c = 0; c < 8; c++) m[col][c] *= d;
        for (int r = 0; r < 4; r++) {
            if (r == col) continue;
            float f = m[r][col];
            for (int c = 0; c < 8; c++) m[r][c] -= f * m[col][c];
        }
    }
    for (int r = 0; r < 3; r++)
        for (int c = 0; c < 4; c++)
            g_inv[r * 4 + c] = m[r][c + 4];
}

__device__ __forceinline__ unsigned q8(float v) {
    int u = __float2int_rn(v * U_SCALE);
    return (unsigned)min(max(u, 0), 255);
}

__device__ __forceinline__ unsigned make_quad(float a, float b, float c, float d) {
    return q8(a) | (q8(b) << 8) | (q8(c) << 16) | (q8(d) << 24);
}

__device__ __forceinline__ float sig(float d) {
    return 1.0f / (1.0f + __expf(0.3f - d));
}

// ---------------------------------------------------------------------------
// Pack kernel: sigmoid + transpose + (x,y)-face u8-quad pack.
// Block (32,8): output brick x:32, z:32, y:8 from 9 smem y-planes (x-halo 1).
// grid = (8 x-tiles, 8 z-tiles, 32 y-groups). Read phase register-batched
// (12 independent LDGs in flight per thread) for high MLP.
// ---------------------------------------------------------------------------
__global__ void pack_kernel(const float* __restrict__ dens,
                            const float* __restrict__ affine) {
    if (blockIdx.x == 0 && blockIdx.y == 0 && blockIdx.z == 0 &&
        threadIdx.x == 0 && threadIdx.y == 0)
        invert_affine(affine);

    __shared__ float s[9][33][33];   // [y-local][x-local][z-local]
    const int tx = threadIdx.x;      // 32 (z lanes on load, x lanes on store)
    const int ty = threadIdx.y;      // 8
    const int x0 = blockIdx.x * 32;
    const int z0 = blockIdx.y * 32;
    const int y0 = blockIdx.z * 8;

    // --- read phase: 9 y-planes in 3 groups of 3; each group issues
    // 12 (+halo) independent predicated loads before any consumes. ---
#pragma unroll
    for (int yg = 0; yg < 3; yg++) {
        float v[3][4];
        float v32[3];
#pragma unroll
        for (int j = 0; j < 3; j++) {
            int yl = yg * 3 + j;
            int y  = y0 + yl;
            bool yok = (y < DIM);
#pragma unroll
            for (int k = 0; k < 4; k++) {
                int x = x0 + ty + k * 8;
                bool ok = yok && (x < DIM);
                v[j][k] = ok ? dens[((x * DIM) + y) * DIM + z0 + tx] : 1e30f;
                if (!ok) v[j][k] = 1e30f;
            }
            if (ty == 0) {
                int x = x0 + 32;
                bool ok = yok && (x < DIM);
                v32[j] = ok ? dens[((x * DIM) + y) * DIM + z0 + tx] : 1e30f;
                if (!ok) v32[j] = 1e30f;
            }
        }
#pragma unroll
        for (int j = 0; j < 3; j++) {
            int yl = yg * 3 + j;
#pragma unroll
            for (int k = 0; k < 4; k++) {
                float d = v[j][k];
                s[yl][ty + k * 8][tx] = (d > 1e29f) ? 0.0f : sig(d);
            }
            if (ty == 0) {
                float d = v32[j];
                s[yl][32][tx] = (d > 1e29f) ? 0.0f : sig(d);
            }
        }
    }
    __syncthreads();

    // --- write phase: u8 quads, lanes = x-local (coalesced 128B/warp) ---
#pragma unroll
    for (int yl = 0; yl < 8; yl++) {
        int yp = y0 + yl + 2;
#pragma unroll
        for (int zi = 0; zi < 4; zi++) {
            int zl = ty + zi * 8;
            int o = ((z0 + zl + 2) * PITCH + yp) * PITCH;
            g_vol[o + x0 + tx + 2] =
                make_quad(s[yl][tx][zl],     s[yl][tx + 1][zl],
                          s[yl + 1][tx][zl], s[yl + 1][tx + 1][zl]);
            if (x0 == 0 && tx == 0)  // padded x=1: orig x=-1 pair
                g_vol[o + 1] =
                    make_quad(0.0f, s[yl][0][zl], 0.0f, s[yl + 1][0][zl]);
        }
    }
    // padded y=1 row (orig y=-1): quad = (0,0, v(x,0), v(x+1,0))
    if (y0 == 0) {
#pragma unroll
        for (int zi = 0; zi < 4; zi++) {
            int zl = ty + zi * 8;
            int o = ((z0 + zl + 2) * PITCH + 1) * PITCH;
            g_vol[o + x0 + tx + 2] =
                make_quad(0.0f, 0.0f, s[0][tx][zl], s[0][tx + 1][zl]);
            if (x0 == 0 && tx == 0)
                g_vol[o + 1] = make_quad(0.0f, 0.0f, 0.0f, s[0][0][zl]);
        }
    }
}

// ---------------------------------------------------------------------------
// Ray march: 8 lanes per ray, round-robin sample partition, 2 x LDG.32 per
// tap. Incremental coordinates (3 FADD/tap), PRMT u8->half column pairs,
// SIMD fp16 x-lerp (HSUB2+HFMA2), fp32 y/z lerp, shfl reduce, one per-ray
// affine correction (subtract 1024*N, scale by 0.65/255).
// ---------------------------------------------------------------------------
#define LANES_PER_RAY 8

__global__ void drr_kernel(const float* __restrict__ src,
                           const float* __restrict__ tgt,
                           const int* __restrict__ npts,
                           float* __restrict__ out,
                           int nrays) {
    int t    = blockIdx.x * blockDim.x + threadIdx.x;
    int ray  = t >> 3;
    int lane = t & 7;
    bool valid = (ray < nrays);

    float acc = 0.0f;       // accumulates w = 1024 + lerp(u)
    float raylen = 0.0f;
    float nin = 0.0f;       // in-box sample count (same for all lanes of ray)
    int P = 500;

    if (valid) {
        P = npts[0];
        float Sx = src[ray * 3 + 0], Sy = src[ray * 3 + 1], Sz = src[ray * 3 + 2];
        float Tx = tgt[ray * 3 + 0], Ty = tgt[ray * 3 + 1], Tz = tgt[ray * 3 + 2];

        float wx = Tx - Sx, wy = Ty - Sy, wz = Tz - Sz;
        raylen = sqrtf(wx * wx + wy * wy + wz * wz);

        // world -> voxel index space
        float sx = g_inv[0] * Sx + g_inv[1] * Sy + g_inv[2]  * Sz + g_inv[3];
        float sy = g_inv[4] * Sx + g_inv[5] * Sy + g_inv[6]  * Sz + g_inv[7];
        float sz = g_inv[8] * Sx + g_inv[9] * Sy + g_inv[10] * Sz + g_inv[11];
        float ex = g_inv[0] * Tx + g_inv[1] * Ty + g_inv[2]  * Tz + g_inv[3];
        float ey = g_inv[4] * Tx + g_inv[5] * Ty + g_inv[6]  * Tz + g_inv[7];
        float ez = g_inv[8] * Tx + g_inv[9] * Ty + g_inv[10] * Tz + g_inv[11];

        float dx = ex - sx, dy = ey - sy, dz = ez - sz;

        // slab-clip alpha to open support box (-1, 256), slightly widened
        float a0 = 0.0f, a1 = 1.0f;
        {
            const float lo = -1.002f, hi = 256.002f;
            float ss[3] = {sx, sy, sz};
            float dd[3] = {dx, dy, dz};
#pragma unroll
            for (int ax = 0; ax < 3; ax++) {
                float s = ss[ax], d = dd[ax];
                if (fabsf(d) < 1e-12f) {
                    if (s <= lo || s >= hi) { a0 = 1.0f; a1 = 0.0f; }
                } else {
                    float inv = 1.0f / d;
                    float ta = (lo - s) * inv;
                    float tb = (hi - s) * inv;
                    a0 = fmaxf(a0, fminf(ta, tb));
                    a1 = fminf(a1, fmaxf(ta, tb));
                }
            }
        }

        float invPm1 = 1.0f / (float)(P - 1);
        int plo = max(0, (int)ceilf(a0 * (float)(P - 1)));
        int phi = min(P - 1, (int)floorf(a1 * (float)(P - 1)));

        int myfirst = plo + lane;
        if (phi >= plo) {
            nin = (float)(phi - plo + 1);

            if (myfirst <= phi) {
                int iters = (phi - myfirst) / LANES_PER_RAY + 1;

                // starting position (padded index space: +2 shift) and the
                // per-iteration step (8 samples ahead)
                float af = (float)myfirst * invPm1;
                float X = fmaf(af, dx, sx + 2.0f);
                float Y = fmaf(af, dy, sy + 2.0f);
                float Z = fmaf(af, dz, sz + 2.0f);
                float stepf = (float)LANES_PER_RAY * invPm1;
                float sdx = stepf * dx, sdy = stepf * dy, sdz = stepf * dz;

#pragma unroll 4
                for (int k = 0; k < iters; ++k) {
                    // X,Y,Z >= ~1 by the clip, so trunc == floor
                    int ix = (int)X, iy = (int)Y, iz = (int)Z;
                    float ux = X - (float)ix;
                    float uy = Y - (float)iy;
                    float uz = Z - (float)iz;

                    int base = (iz * PITCH + iy) * PITCH + ix;
                    unsigned q0 = __ldg(&g_vol[base]);            // face z
                    unsigned q1 = __ldg(&g_vol[base + PITCH2]);   // face z+1

                    // column pairs: lo = (1024+u(x,y), 1024+u(x,y+1))
                    //               hi = (1024+u(x+1,y), 1024+u(x+1,y+1))
                    unsigned lo0 = __byte_perm(q0, 0x64646464u, 0x5240);
                    unsigned hi0 = __byte_perm(q0, 0x64646464u, 0x5341);
                    unsigned lo1 = __byte_perm(q1, 0x64646464u, 0x5240);
                    unsigned hi1 = __byte_perm(q1, 0x64646464u, 0x5341);

                    __half2 l0 = *reinterpret_cast<__half2*>(&lo0);
                    __half2 h0 = *reinterpret_cast<__half2*>(&hi0);
                    __half2 l1 = *reinterpret_cast<__half2*>(&lo1);
                    __half2 h1 = *reinterpret_cast<__half2*>(&hi1);

                    // SIMD x-lerp: both y-rows at once (diffs exact in fp16,
                    // one fused rounding <= 0.5u)
                    __half2 ux2 = __float2half2_rn(ux);
                    __half2 xl0 = __hfma2(ux2, __hsub2(h0, l0), l0);
                    __half2 xl1 = __hfma2(ux2, __hsub2(h1, l1), l1);

                    float2 f0 = __half22float2(xl0);
                    float2 f1 = __half22float2(xl1);

                    // y-lerp, z-lerp in fp32
                    float w0 = fmaf(uy, f0.y - f0.x, f0.x);
                    float w1 = fmaf(uy, f1.y - f1.x, f1.x);
                    acc += fmaf(uz, w1 - w0, w0);

                    X += sdx; Y += sdy; Z += sdz;
                }
            }
        }
    }

    // reduce across the 8 lanes of this ray
    acc += __shfl_xor_sync(0xffffffffu, acc, 1);
    acc += __shfl_xor_sync(0xffffffffu, acc, 2);
    acc += __shfl_xor_sync(0xffffffffu, acc, 4);

    if (valid && lane == 0) {
        float s = (acc - 1024.0f * nin) * V_SCALE;  // back to v-scale sum
        out[ray] = s * raylen / (float)P;
    }
}

// ---------------------------------------------------------------------------
// Launch
// ---------------------------------------------------------------------------
extern "C" void kernel_launch(void* const* d_in, const int* in_sizes, int n_in,
                              void* d_out, int out_size) {
    const float* density = (const float*)d_in[0];
    const float* source  = (const float*)d_in[1];
    const float* target  = (const float*)d_in[2];
    const float* affine  = (const float*)d_in[3];
    const int*   npts    = (const int*)d_in[4];

    float* out = (float*)d_out;
    int nrays = in_sizes[1] / 3;

    // 1) sigmoid + transpose + u8 quad pack (+ affine inverse on thread 0)
    pack_kernel<<<dim3(8, 8, 32), dim3(32, 8)>>>(density, affine);

    // 2) ray integration, 8 lanes per ray
    int threads = nrays * LANES_PER_RAY;
    drr_kernel<<<(threads + 255) / 256, 256>>>(source, target, npts, out, nrays);
}

// round 9
// speedup vs baseline: 1.0809x; 1.0809x over previous
#include <cuda_runtime.h>
#include <cuda_fp16.h>
#include <math.h>

// ---------------------------------------------------------------------------
// DRR ray integration, GB300.
// g_vol[z][y][x] holds a 2x2 (x,y)-face quad of the regulated density,
// quantized to u8:  u = round( v * 255/0.65 ),  v = sigmoid(d - 0.3).
//   quad bytes = ( u(x,y), u(x+1,y), u(x,y+1), u(x+1,y+1) )  in one uint.
// One trilinear tap = 2 x LDG.32 (faces at z and z+1); 70 MB volume is
// mostly L2-resident. u=0 maps to v=0 so zero-padded borders are exact.
// Decode: PRMT builds half2(1024+u) COLUMN pairs; one HSUB2+HFMA2 does the
// x-lerp for both y-rows simultaneously (diffs exact in fp16, one rounding
// <= 0.5u). y/z lerp in fp32. Per-tap coordinates are computed独立ly from p
// (a = p*invPm1) so unrolled taps stay independent -> high memory MLP.
// The affine (1024 offset, 0.65/255 scale) is corrected once per ray.
// ---------------------------------------------------------------------------

#define DIM 256
#define PITCH 260
#define PITCH2 (PITCH * PITCH)

#define V_SCALE (0.65f / 255.0f)      // v = u * V_SCALE
#define U_SCALE (255.0f / 0.65f)      // u = v * U_SCALE

__device__ unsigned g_vol[PITCH * PITCH * PITCH];  // ~70 MB, .bss zero-init
__device__ float    g_inv[12];                      // inv(affine)[:3,:4]

// ---------------------------------------------------------------------------
// 4x4 Gauss-Jordan inverse (single thread; runs inside pack kernel).
// ---------------------------------------------------------------------------
__device__ void invert_affine(const float* __restrict__ A) {
    float m[4][8];
#pragma unroll
    for (int r = 0; r < 4; r++)
#pragma unroll
        for (int c = 0; c < 4; c++) {
            m[r][c]     = A[r * 4 + c];
            m[r][c + 4] = (r == c) ? 1.0f : 0.0f;
        }
    for (int col = 0; col < 4; col++) {
        int piv = col;
        float best = fabsf(m[col][col]);
        for (int r = col + 1; r < 4; r++) {
            float v = fabsf(m[r][col]);
            if (v > best) { best = v; piv = r; }
        }
        if (piv != col)
            for (int c = 0; c < 8; c++) {
                float t = m[col][c]; m[col][c] = m[piv][c]; m[piv][c] = t;
            }
        float d = 1.0f / m[col][col];
        for (int c = 0; c < 8; c++) m[col][c] *= d;
        for (int r = 0; r < 4; r++) {
            if (r == col) continue;
            float f = m[r][col];
            for (int c = 0; c < 8; c++) m[r][c] -= f * m[col][c];
        }
    }
    for (int r = 0; r < 3; r++)
        for (int c = 0; c < 4; c++)
            g_inv[r * 4 + c] = m[r][c + 4];
}

__device__ __forceinline__ unsigned q8(float v) {
    int u = __float2int_rn(v * U_SCALE);
    return (unsigned)min(max(u, 0), 255);
}

__device__ __forceinline__ unsigned make_quad(float a, float b, float c, float d) {
    return q8(a) | (q8(b) << 8) | (q8(c) << 16) | (q8(d) << 24);
}

__device__ __forceinline__ float sig(float d) {
    return 1.0f / (1.0f + __expf(0.3f - d));
}

// ---------------------------------------------------------------------------
// Pack kernel: sigmoid + transpose + (x,y)-face u8-quad pack.
// Block (32,8): output brick x:32, z:32, y:8 from 9 smem y-planes (x-halo 1).
// grid = (8 x-tiles, 8 z-tiles, 32 y-groups). Read phase register-batched
// (12 independent LDGs in flight per thread) for high MLP.
// ---------------------------------------------------------------------------
__global__ void pack_kernel(const float* __restrict__ dens,
                            const float* __restrict__ affine) {
    if (blockIdx.x == 0 && blockIdx.y == 0 && blockIdx.z == 0 &&
        threadIdx.x == 0 && threadIdx.y == 0)
        invert_affine(affine);

    __shared__ float s[9][33][33];   // [y-local][x-local][z-local]
    const int tx = threadIdx.x;      // 32 (z lanes on load, x lanes on store)
    const int ty = threadIdx.y;      // 8
    const int x0 = blockIdx.x * 32;
    const int z0 = blockIdx.y * 32;
    const int y0 = blockIdx.z * 8;

    // --- read phase: 9 y-planes in 3 groups of 3; each group issues
    // 12 (+halo) independent predicated loads before any consumes. ---
#pragma unroll
    for (int yg = 0; yg < 3; yg++) {
        float v[3][4];
        float v32[3];
#pragma unroll
        for (int j = 0; j < 3; j++) {
            int yl = yg * 3 + j;
            int y  = y0 + yl;
            bool yok = (y < DIM);
#pragma unroll
            for (int k = 0; k < 4; k++) {
                int x = x0 + ty + k * 8;
                bool ok = yok && (x < DIM);
                v[j][k] = ok ? dens[((x * DIM) + y) * DIM + z0 + tx] : 1e30f;
                if (!ok) v[j][k] = 1e30f;
            }
            if (ty == 0) {
                int x = x0 + 32;
                bool ok = yok && (x < DIM);
                v32[j] = ok ? dens[((x * DIM) + y) * DIM + z0 + tx] : 1e30f;
                if (!ok) v32[j] = 1e30f;
            }
        }
#pragma unroll
        for (int j = 0; j < 3; j++) {
            int yl = yg * 3 + j;
#pragma unroll
            for (int k = 0; k < 4; k++) {
                float d = v[j][k];
                s[yl][ty + k * 8][tx] = (d > 1e29f) ? 0.0f : sig(d);
            }
            if (ty == 0) {
                float d = v32[j];
                s[yl][32][tx] = (d > 1e29f) ? 0.0f : sig(d);
            }
        }
    }
    __syncthreads();

    // --- write phase: u8 quads, lanes = x-local (coalesced 128B/warp) ---
#pragma unroll
    for (int yl = 0; yl < 8; yl++) {
        int yp = y0 + yl + 2;
#pragma unroll
        for (int zi = 0; zi < 4; zi++) {
            int zl = ty + zi * 8;
            int o = ((z0 + zl + 2) * PITCH + yp) * PITCH;
            g_vol[o + x0 + tx + 2] =
                make_quad(s[yl][tx][zl],     s[yl][tx + 1][zl],
                          s[yl + 1][tx][zl], s[yl + 1][tx + 1][zl]);
            if (x0 == 0 && tx == 0)  // padded x=1: orig x=-1 pair
                g_vol[o + 1] =
                    make_quad(0.0f, s[yl][0][zl], 0.0f, s[yl + 1][0][zl]);
        }
    }
    // padded y=1 row (orig y=-1): quad = (0,0, v(x,0), v(x+1,0))
    if (y0 == 0) {
#pragma unroll
        for (int zi = 0; zi < 4; zi++) {
            int zl = ty + zi * 8;
            int o = ((z0 + zl + 2) * PITCH + 1) * PITCH;
            g_vol[o + x0 + tx + 2] =
                make_quad(0.0f, 0.0f, s[0][tx][zl], s[0][tx + 1][zl]);
            if (x0 == 0 && tx == 0)
                g_vol[o + 1] = make_quad(0.0f, 0.0f, 0.0f, s[0][0][zl]);
        }
    }
}

// ---------------------------------------------------------------------------
// Ray march: 8 lanes per ray, round-robin sample partition, 2 x LDG.32 per
// tap, independent per-tap coordinates (unrolled taps overlap in LSU),
// half2 SIMD x-lerp, fp32 y/z lerp, shfl reduce, one per-ray affine
// correction (subtract 1024*N, scale by 0.65/255).
// ---------------------------------------------------------------------------
#define LANES_PER_RAY 8

__global__ void drr_kernel(const float* __restrict__ src,
                           const float* __restrict__ tgt,
                           const int* __restrict__ npts,
                           float* __restrict__ out,
                           int nrays) {
    int t    = blockIdx.x * blockDim.x + threadIdx.x;
    int ray  = t >> 3;
    int lane = t & 7;
    bool valid = (ray < nrays);

    float acc = 0.0f;       // accumulates w = 1024 + lerp(u)
    float raylen = 0.0f;
    float nin = 0.0f;       // in-box sample count (same for all lanes of ray)
    int P = 500;

    if (valid) {
        P = npts[0];
        float Sx = src[ray * 3 + 0], Sy = src[ray * 3 + 1], Sz = src[ray * 3 + 2];
        float Tx = tgt[ray * 3 + 0], Ty = tgt[ray * 3 + 1], Tz = tgt[ray * 3 + 2];

        float wx = Tx - Sx, wy = Ty - Sy, wz = Tz - Sz;
        raylen = sqrtf(wx * wx + wy * wy + wz * wz);

        // world -> voxel index space
        float sx = g_inv[0] * Sx + g_inv[1] * Sy + g_inv[2]  * Sz + g_inv[3];
        float sy = g_inv[4] * Sx + g_inv[5] * Sy + g_inv[6]  * Sz + g_inv[7];
        float sz = g_inv[8] * Sx + g_inv[9] * Sy + g_inv[10] * Sz + g_inv[11];
        float ex = g_inv[0] * Tx + g_inv[1] * Ty + g_inv[2]  * Tz + g_inv[3];
        float ey = g_inv[4] * Tx + g_inv[5] * Ty + g_inv[6]  * Tz + g_inv[7];
        float ez = g_inv[8] * Tx + g_inv[9] * Ty + g_inv[10] * Tz + g_inv[11];

        float dx = ex - sx, dy = ey - sy, dz = ez - sz;

        // slab-clip alpha to open support box (-1, 256), slightly widened
        float a0 = 0.0f, a1 = 1.0f;
        {
            const float lo = -1.002f, hi = 256.002f;
            float ss[3] = {sx, sy, sz};
            float dd[3] = {dx, dy, dz};
#pragma unroll
            for (int ax = 0; ax < 3; ax++) {
                float s = ss[ax], d = dd[ax];
                if (fabsf(d) < 1e-12f) {
                    if (s <= lo || s >= hi) { a0 = 1.0f; a1 = 0.0f; }
                } else {
                    float inv = 1.0f / d;
                    float ta = (lo - s) * inv;
                    float tb = (hi - s) * inv;
                    a0 = fmaxf(a0, fminf(ta, tb));
                    a1 = fminf(a1, fmaxf(ta, tb));
                }
            }
        }

        float invPm1 = 1.0f / (float)(P - 1);
        int plo = max(0, (int)ceilf(a0 * (float)(P - 1)));
        int phi = min(P - 1, (int)floorf(a1 * (float)(P - 1)));

        if (phi >= plo) {
            nin = (float)(phi - plo + 1);
            float sx2 = sx + 2.0f, sy2 = sy + 2.0f, sz2 = sz + 2.0f;

#pragma unroll 4
            for (int p = plo + lane; p <= phi; p += LANES_PER_RAY) {
                float a = (float)p * invPm1;
                float X = fmaf(a, dx, sx2);
                float Y = fmaf(a, dy, sy2);
                float Z = fmaf(a, dz, sz2);

                // coords >= 0.998 > 0 by the clip, so trunc == floor
                int ix = (int)X, iy = (int)Y, iz = (int)Z;
                float ux = X - (float)ix;
                float uy = Y - (float)iy;
                float uz = Z - (float)iz;

                int base = (iz * PITCH + iy) * PITCH + ix;
                unsigned q0 = __ldg(&g_vol[base]);            // face z
                unsigned q1 = __ldg(&g_vol[base + PITCH2]);   // face z+1

                // column pairs: lo = (1024+u(x,y),  1024+u(x,y+1))
                //               hi = (1024+u(x+1,y),1024+u(x+1,y+1))
                unsigned lo0 = __byte_perm(q0, 0x64646464u, 0x5240);
                unsigned hi0 = __byte_perm(q0, 0x64646464u, 0x5341);
                unsigned lo1 = __byte_perm(q1, 0x64646464u, 0x5240);
                unsigned hi1 = __byte_perm(q1, 0x64646464u, 0x5341);

                __half2 l0 = *reinterpret_cast<__half2*>(&lo0);
                __half2 h0 = *reinterpret_cast<__half2*>(&hi0);
                __half2 l1 = *reinterpret_cast<__half2*>(&lo1);
                __half2 h1 = *reinterpret_cast<__half2*>(&hi1);

                // SIMD x-lerp: both y-rows at once (diffs exact in fp16,
                // one fused rounding <= 0.5u)
                __half2 ux2 = __float2half2_rn(ux);
                __half2 xl0 = __hfma2(ux2, __hsub2(h0, l0), l0);
                __half2 xl1 = __hfma2(ux2, __hsub2(h1, l1), l1);

                float2 f0 = __half22float2(xl0);
                float2 f1 = __half22float2(xl1);

                // y-lerp, z-lerp in fp32
                float w0 = fmaf(uy, f0.y - f0.x, f0.x);
                float w1 = fmaf(uy, f1.y - f1.x, f1.x);
                acc += fmaf(uz, w1 - w0, w0);
            }
        }
    }

    // reduce across the 8 lanes of this ray
    acc += __shfl_xor_sync(0xffffffffu, acc, 1);
    acc += __shfl_xor_sync(0xffffffffu, acc, 2);
    acc += __shfl_xor_sync(0xffffffffu, acc, 4);

    if (valid && lane == 0) {
        float s = (acc - 1024.0f * nin) * V_SCALE;  // back to v-scale sum
        out[ray] = s * raylen / (float)P;
    }
}

// ---------------------------------------------------------------------------
// Launch
// ---------------------------------------------------------------------------
extern "C" void kernel_launch(void* const* d_in, const int* in_sizes, int n_in,
                              void* d_out, int out_size) {
    const float* density = (const float*)d_in[0];
    const float* source  = (const float*)d_in[1];
    const float* target  = (const float*)d_in[2];
    const float* affine  = (const float*)d_in[3];
    const int*   npts    = (const int*)d_in[4];

    float* out = (float*)d_out;
    int nrays = in_sizes[1] / 3;

    // 1) sigmoid + transpose + u8 quad pack (+ affine inverse on thread 0)
    pack_kernel<<<dim3(8, 8, 32), dim3(32, 8)>>>(density, affine);

    // 2) ray integration, 8 lanes per ray
    int threads = nrays * LANES_PER_RAY;
    drr_kernel<<<(threads + 255) / 256, 256>>>(source, target, npts, out, nrays);
}

// round 10
// speedup vs baseline: 1.1049x; 1.0222x over previous
#include <cuda_runtime.h>
#include <cuda_fp16.h>
#include <math.h>

// ---------------------------------------------------------------------------
// DRR ray integration, GB300.
// g_vol[z][y][x] holds a 2x2 (x,y)-face quad of the regulated density,
// quantized to u8:  u = round( v * 255/0.65 ),  v = sigmoid(d - 0.3).
//   quad bytes = ( u(x,y), u(x+1,y), u(x,y+1), u(x+1,y+1) )  in one uint.
// One trilinear tap = 2 x LDG.32 (faces at z and z+1); 70 MB volume is
// mostly L2-resident. u=0 maps to v=0 so zero-padded borders are exact.
// Decode: PRMT builds half2(1024+u) row pairs; lerp in fp32; the affine
// (1024 offset, 0.65/255 scale) is corrected once per ray.
// ---------------------------------------------------------------------------

#define DIM 256
#define PITCH 260
#define PITCH2 (PITCH * PITCH)

#define V_SCALE (0.65f / 255.0f)      // v = u * V_SCALE
#define U_SCALE (255.0f / 0.65f)      // u = v * U_SCALE

__device__ unsigned g_vol[PITCH * PITCH * PITCH];  // ~70 MB, .bss zero-init
__device__ float    g_inv[12];                      // inv(affine)[:3,:4]

// ---------------------------------------------------------------------------
// 4x4 Gauss-Jordan inverse (single thread; runs inside pack kernel).
// ---------------------------------------------------------------------------
__device__ void invert_affine(const float* __restrict__ A) {
    float m[4][8];
#pragma unroll
    for (int r = 0; r < 4; r++)
#pragma unroll
        for (int c = 0; c < 4; c++) {
            m[r][c]     = A[r * 4 + c];
            m[r][c + 4] = (r == c) ? 1.0f : 0.0f;
        }
    for (int col = 0; col < 4; col++) {
        int piv = col;
        float best = fabsf(m[col][col]);
        for (int r = col + 1; r < 4; r++) {
            float v = fabsf(m[r][col]);
            if (v > best) { best = v; piv = r; }
        }
        if (piv != col)
            for (int c = 0; c < 8; c++) {
                float t = m[col][c]; m[col][c] = m[piv][c]; m[piv][c] = t;
            }
        float d = 1.0f / m[col][col];
        for (int c = 0; c < 8; c++) m[col][c] *= d;
        for (int r = 0; r < 4; r++) {
            if (r == col) continue;
            float f = m[r][col];
            for (int c = 0; c < 8; c++) m[r][c] -= f * m[col][c];
        }
    }
    for (int r = 0; r < 3; r++)
        for (int c = 0; c < 4; c++)
            g_inv[r * 4 + c] = m[r][c + 4];
}

__device__ __forceinline__ unsigned q8(float v) {
    int u = __float2int_rn(v * U_SCALE);
    return (unsigned)min(max(u, 0), 255);
}

__device__ __forceinline__ float sig(float d) {
    return 1.0f / (1.0f + __expf(0.3f - d));
}

// quantize with out-of-range sentinel -> 0 (zero padding semantics)
__device__ __forceinline__ unsigned char q8s(float d) {
    return (d > 1e29f) ? (unsigned char)0 : (unsigned char)q8(sig(d));
}

// ---------------------------------------------------------------------------
// Pack kernel: sigmoid + quantize + transpose + (x,y)-face u8-quad pack.
// Block (32,8): output brick x:32, z:32, y:8 from 9 smem y-planes (x-halo 1).
// grid = (8 x-tiles, 8 z-tiles, 32 y-groups). Read phase register-batched
// (12 independent LDGs in flight per thread). smem is u8 (9.8 KB) so many
// blocks are resident -> DRAM read latency hidden.
// ---------------------------------------------------------------------------
__global__ void pack_kernel(const float* __restrict__ dens,
                            const float* __restrict__ affine) {
    if (blockIdx.x == 0 && blockIdx.y == 0 && blockIdx.z == 0 &&
        threadIdx.x == 0 && threadIdx.y == 0)
        invert_affine(affine);

    __shared__ unsigned char s8[9][33][33];  // [y-local][x-local][z-local]
    const int tx = threadIdx.x;      // 32 (z lanes on load, x lanes on store)
    const int ty = threadIdx.y;      // 8
    const int x0 = blockIdx.x * 32;
    const int z0 = blockIdx.y * 32;
    const int y0 = blockIdx.z * 8;

    // --- read phase: 9 y-planes in 3 groups of 3; each group issues
    // 12 (+halo) independent predicated loads before any consumes. ---
#pragma unroll
    for (int yg = 0; yg < 3; yg++) {
        float v[3][4];
        float v32[3];
#pragma unroll
        for (int j = 0; j < 3; j++) {
            int yl = yg * 3 + j;
            int y  = y0 + yl;
            bool yok = (y < DIM);
#pragma unroll
            for (int k = 0; k < 4; k++) {
                int x = x0 + ty + k * 8;
                bool ok = yok && (x < DIM);
                v[j][k] = ok ? dens[((x * DIM) + y) * DIM + z0 + tx] : 1e30f;
                if (!ok) v[j][k] = 1e30f;
            }
            if (ty == 0) {
                int x = x0 + 32;
                bool ok = yok && (x < DIM);
                v32[j] = ok ? dens[((x * DIM) + y) * DIM + z0 + tx] : 1e30f;
                if (!ok) v32[j] = 1e30f;
            }
        }
#pragma unroll
        for (int j = 0; j < 3; j++) {
            int yl = yg * 3 + j;
#pragma unroll
            for (int k = 0; k < 4; k++)
                s8[yl][ty + k * 8][tx] = q8s(v[j][k]);
            if (ty == 0)
                s8[yl][32][tx] = q8s(v32[j]);
        }
    }
    __syncthreads();

    // --- write phase: u8 quads, lanes = x-local (coalesced 128B/warp) ---
#pragma unroll
    for (int yl = 0; yl < 8; yl++) {
        int yp = y0 + yl + 2;
#pragma unroll
        for (int zi = 0; zi < 4; zi++) {
            int zl = ty + zi * 8;
            int o = ((z0 + zl + 2) * PITCH + yp) * PITCH;
            unsigned b0 = s8[yl][tx][zl];
            unsigned b1 = s8[yl][tx + 1][zl];
            unsigned b2 = s8[yl + 1][tx][zl];
            unsigned b3 = s8[yl + 1][tx + 1][zl];
            g_vol[o + x0 + tx + 2] = b0 | (b1 << 8) | (b2 << 16) | (b3 << 24);
            if (x0 == 0 && tx == 0) {  // padded x=1: orig x=-1 pair
                unsigned c1 = s8[yl][0][zl];
                unsigned c3 = s8[yl + 1][0][zl];
                g_vol[o + 1] = (c1 << 8) | (c3 << 24);
            }
        }
    }
    // padded y=1 row (orig y=-1): quad = (0,0, v(x,0), v(x+1,0))
    if (y0 == 0) {
#pragma unroll
        for (int zi = 0; zi < 4; zi++) {
            int zl = ty + zi * 8;
            int o = ((z0 + zl + 2) * PITCH + 1) * PITCH;
            unsigned b2 = s8[0][tx][zl];
            unsigned b3 = s8[0][tx + 1][zl];
            g_vol[o + x0 + tx + 2] = (b2 << 16) | (b3 << 24);
            if (x0 == 0 && tx == 0) {
                unsigned c3 = s8[0][0][zl];
                g_vol[o + 1] = (c3 << 24);
            }
        }
    }
}

// ---------------------------------------------------------------------------
// Ray march: 8 lanes per ray, round-robin sample partition, 2 x LDG.32 per
// tap, PRMT u8->half decode (w = 1024 + u), fp32 lerp, shfl reduce, and a
// single per-ray affine correction. 128-thread blocks for fine-grained load
// balance (per-ray sample counts vary 0..500).
// ---------------------------------------------------------------------------
#define LANES_PER_RAY 8

__global__ void drr_kernel(const float* __restrict__ src,
                           const float* __restrict__ tgt,
                           const int* __restrict__ npts,
                           float* __restrict__ out,
                           int nrays) {
    int t    = blockIdx.x * blockDim.x + threadIdx.x;
    int ray  = t >> 3;
    int lane = t & 7;
    bool valid = (ray < nrays);

    float acc = 0.0f;       // accumulates w = 1024 + lerp(u)
    float raylen = 0.0f;
    float nin = 0.0f;       // in-box sample count (same for all lanes of ray)
    int P = 500;

    if (valid) {
        P = npts[0];
        float Sx = src[ray * 3 + 0], Sy = src[ray * 3 + 1], Sz = src[ray * 3 + 2];
        float Tx = tgt[ray * 3 + 0], Ty = tgt[ray * 3 + 1], Tz = tgt[ray * 3 + 2];

        float wx = Tx - Sx, wy = Ty - Sy, wz = Tz - Sz;
        raylen = sqrtf(wx * wx + wy * wy + wz * wz);

        // world -> voxel index space
        float sx = g_inv[0] * Sx + g_inv[1] * Sy + g_inv[2]  * Sz + g_inv[3];
        float sy = g_inv[4] * Sx + g_inv[5] * Sy + g_inv[6]  * Sz + g_inv[7];
        float sz = g_inv[8] * Sx + g_inv[9] * Sy + g_inv[10] * Sz + g_inv[11];
        float ex = g_inv[0] * Tx + g_inv[1] * Ty + g_inv[2]  * Tz + g_inv[3];
        float ey = g_inv[4] * Tx + g_inv[5] * Ty + g_inv[6]  * Tz + g_inv[7];
        float ez = g_inv[8] * Tx + g_inv[9] * Ty + g_inv[10] * Tz + g_inv[11];

        float dx = ex - sx, dy = ey - sy, dz = ez - sz;

        // slab-clip alpha to open support box (-1, 256), slightly widened
        float a0 = 0.0f, a1 = 1.0f;
        {
            const float lo = -1.002f, hi = 256.002f;
            float ss[3] = {sx, sy, sz};
            float dd[3] = {dx, dy, dz};
#pragma unroll
            for (int ax = 0; ax < 3; ax++) {
                float s = ss[ax], d = dd[ax];
                if (fabsf(d) < 1e-12f) {
                    if (s <= lo || s >= hi) { a0 = 1.0f; a1 = 0.0f; }
                } else {
                    float inv = 1.0f / d;
                    float ta = (lo - s) * inv;
                    float tb = (hi - s) * inv;
                    a0 = fmaxf(a0, fminf(ta, tb));
                    a1 = fminf(a1, fmaxf(ta, tb));
                }
            }
        }

        float invPm1 = 1.0f / (float)(P - 1);
        int plo = max(0, (int)ceilf(a0 * (float)(P - 1)));
        int phi = min(P - 1, (int)floorf(a1 * (float)(P - 1)));

        if (phi >= plo) {
            nin = (float)(phi - plo + 1);
            float sx2 = sx + 2.0f, sy2 = sy + 2.0f, sz2 = sz + 2.0f;

#pragma unroll 4
            for (int p = plo + lane; p <= phi; p += LANES_PER_RAY) {
                float a = (float)p * invPm1;
                float X = fmaf(a, dx, sx2);
                float Y = fmaf(a, dy, sy2);
                float Z = fmaf(a, dz, sz2);

                // coords >= ~1 by the clip, so trunc == floor
                int ix = (int)X, iy = (int)Y, iz = (int)Z;
                float ux = X - (float)ix;
                float uy = Y - (float)iy;
                float uz = Z - (float)iz;

                int base = (iz * PITCH + iy) * PITCH + ix;
                unsigned q0 = __ldg(&g_vol[base]);            // face at z
                unsigned q1 = __ldg(&g_vol[base + PITCH2]);   // face at z+1

                // PRMT: half2(1024+b0, 1024+b1) and half2(1024+b2, 1024+b3)
                unsigned p00 = __byte_perm(q0, 0x64646464u, 0x5140);
                unsigned p01 = __byte_perm(q0, 0x64646464u, 0x5342);
                unsigned p10 = __byte_perm(q1, 0x64646464u, 0x5140);
                unsigned p11 = __byte_perm(q1, 0x64646464u, 0x5342);

                float2 a00 = __half22float2(*reinterpret_cast<__half2*>(&p00));
                float2 a01 = __half22float2(*reinterpret_cast<__half2*>(&p01));
                float2 b00 = __half22float2(*reinterpret_cast<__half2*>(&p10));
                float2 b01 = __half22float2(*reinterpret_cast<__half2*>(&p11));

                // lerp x within pairs (w-scale, offset 1024 is lerp-invariant)
                float c0 = fmaf(ux, a00.y - a00.x, a00.x);  // (y  , z  )
                float c1 = fmaf(ux, a01.y - a01.x, a01.x);  // (y+1, z  )
                float d0 = fmaf(ux, b00.y - b00.x, b00.x);  // (y  , z+1)
                float d1 = fmaf(ux, b01.y - b01.x, b01.x);  // (y+1, z+1)

                float w0 = fmaf(uy, c1 - c0, c0);
                float w1 = fmaf(uy, d1 - d0, d0);
                acc += fmaf(uz, w1 - w0, w0);
            }
        }
    }

    // reduce across the 8 lanes of this ray
    acc += __shfl_xor_sync(0xffffffffu, acc, 1);
    acc += __shfl_xor_sync(0xffffffffu, acc, 2);
    acc += __shfl_xor_sync(0xffffffffu, acc, 4);

    if (valid && lane == 0) {
        float s = (acc - 1024.0f * nin) * V_SCALE;  // back to v-scale sum
        out[ray] = s * raylen / (float)P;
    }
}

// ---------------------------------------------------------------------------
// Launch
// ---------------------------------------------------------------------------
extern "C" void kernel_launch(void* const* d_in, const int* in_sizes, int n_in,
                              void* d_out, int out_size) {
    const float* density = (const float*)d_in[0];
    const float* source  = (const float*)d_in[1];
    const float* target  = (const float*)d_in[2];
    const float* affine  = (const float*)d_in[3];
    const int*   npts    = (const int*)d_in[4];

    float* out = (float*)d_out;
    int nrays = in_sizes[1] / 3;

    // 1) sigmoid + quantize + transpose + u8 quad pack
    pack_kernel<<<dim3(8, 8, 32), dim3(32, 8)>>>(density, affine);

    // 2) ray integration, 8 lanes per ray, 128-thread blocks (load balance)
    int threads = nrays * LANES_PER_RAY;
    drr_kernel<<<(threads + 127) / 128, 128>>>(source, target, npts, out, nrays);
}